// round 14
// baseline (speedup 1.0000x reference)
#include <cuda_runtime.h>
#include <cuda_fp16.h>
#include <cstdint>

#define Bb 4
#define Tt 2048
#define Dd 1024
#define Hh 16
#define DH 64
#define MROWS (Bb * Tt)   // 8192

// ---------------------------------------------------------------------------
// Scratch (__device__ globals: allocation-free rule)
// ---------------------------------------------------------------------------
__device__ __half g_qh[(size_t)MROWS * 3 * Dd];     // qkv fp16 hi
__device__ __half g_ql[(size_t)MROWS * 3 * Dd];     // qkv fp16 lo
__device__ float  g_ctx[(size_t)MROWS * Dd];        // attention output fp32
__device__ int8_t g_a8h[(size_t)MROWS * Dd];        // activation int8 hi limb
__device__ int8_t g_a8l[(size_t)MROWS * Dd];        // activation int8 lo limb
__device__ float  g_sa[MROWS];                      // per-row dequant unit
__device__ int8_t g_wqh8[(size_t)3 * Dd * Dd];      // W_qkv^T limbs [3072,1024]
__device__ int8_t g_wql8[(size_t)3 * Dd * Dd];
__device__ float  g_sbq[3 * Dd];
__device__ int8_t g_woh8[(size_t)Dd * Dd];          // W_out^T limbs [1024,1024]
__device__ int8_t g_wol8[(size_t)Dd * Dd];
__device__ float  g_sbo[Dd];
__device__ float  g_cmax[3 * Dd];                   // column-max scratch

// ---------------------------------------------------------------------------
// PTX helpers (plain compute_103-legal)
// ---------------------------------------------------------------------------
__device__ __forceinline__ uint32_t smem_u32(const void* p) {
    uint32_t a;
    asm("{ .reg .u64 t; cvta.to.shared.u64 t, %1; cvt.u32.u64 %0, t; }"
        : "=r"(a) : "l"(p));
    return a;
}
__device__ __forceinline__ void cp_async16(uint32_t saddr, const void* gaddr) {
    asm volatile("cp.async.cg.shared.global [%0], [%1], 16;"
                 :: "r"(saddr), "l"(gaddr));
}
__device__ __forceinline__ void cp_commit() {
    asm volatile("cp.async.commit_group;" ::: "memory");
}
template <int N>
__device__ __forceinline__ void cp_wait() {
    asm volatile("cp.async.wait_group %0;" :: "n"(N) : "memory");
}
__device__ __forceinline__ void ldm_x4(uint32_t* r, uint32_t addr) {
    asm volatile("ldmatrix.sync.aligned.m8n8.x4.shared.b16 {%0,%1,%2,%3}, [%4];"
                 : "=r"(r[0]), "=r"(r[1]), "=r"(r[2]), "=r"(r[3]) : "r"(addr));
}
__device__ __forceinline__ void ldm_x4_t(uint32_t* r, uint32_t addr) {
    asm volatile("ldmatrix.sync.aligned.m8n8.x4.trans.shared.b16 {%0,%1,%2,%3}, [%4];"
                 : "=r"(r[0]), "=r"(r[1]), "=r"(r[2]), "=r"(r[3]) : "r"(addr));
}
__device__ __forceinline__ void mma_f16(float* c, const uint32_t* a, const uint32_t* b) {
    asm volatile("mma.sync.aligned.m16n8k16.row.col.f32.f16.f16.f32 "
                 "{%0,%1,%2,%3}, {%4,%5,%6,%7}, {%8,%9}, {%0,%1,%2,%3};"
                 : "+f"(c[0]), "+f"(c[1]), "+f"(c[2]), "+f"(c[3])
                 : "r"(a[0]), "r"(a[1]), "r"(a[2]), "r"(a[3]), "r"(b[0]), "r"(b[1]));
}
// int8 MMA: k32, s32 accumulate. Same 32-byte K footprint as f16 k16 ->
// identical ldmatrix addressing, data reinterpreted as int8 pairs.
__device__ __forceinline__ void mma_s8(int* c, const uint32_t* a, const uint32_t* b) {
    asm volatile("mma.sync.aligned.m16n8k32.row.col.s32.s8.s8.s32 "
                 "{%0,%1,%2,%3}, {%4,%5,%6,%7}, {%8,%9}, {%0,%1,%2,%3};"
                 : "+r"(c[0]), "+r"(c[1]), "+r"(c[2]), "+r"(c[3])
                 : "r"(a[0]), "r"(a[1]), "r"(a[2]), "r"(a[3]), "r"(b[0]), "r"(b[1]));
}
__device__ __forceinline__ uint32_t pack_h2(__half a, __half b) {
    __half2 h = __halves2half2(a, b);
    return *(uint32_t*)&h;
}
__device__ __forceinline__ float ex2f(float x) {
    float y;
    asm("ex2.approx.ftz.f32 %0, %1;" : "=f"(y) : "f"(x));
    return y;
}

// ---------------------------------------------------------------------------
// Quantization kernels: 15-bit fixed point, 2x int8 limbs, per-row scale.
// ---------------------------------------------------------------------------
__global__ __launch_bounds__(256) void rowquant(const float* __restrict__ X,
                                                int8_t* __restrict__ hi,
                                                int8_t* __restrict__ lo,
                                                float* __restrict__ s, int K)
{
    const int r = blockIdx.x, tid = threadIdx.x;
    const float* x = X + (size_t)r * K;
    float mx = 0.f;
    for (int i = tid; i < K; i += 256) mx = fmaxf(mx, fabsf(x[i]));
#pragma unroll
    for (int w = 16; w; w >>= 1) mx = fmaxf(mx, __shfl_xor_sync(~0u, mx, w, 32));
    __shared__ float red[8];
    if ((tid & 31) == 0) red[tid >> 5] = mx;
    __syncthreads();
    if (tid < 32) {
        float m = (tid < 8) ? red[tid] : 0.f;
#pragma unroll
        for (int w = 4; w; w >>= 1) m = fmaxf(m, __shfl_xor_sync(~0u, m, w, 32));
        if (tid == 0) red[0] = m;
    }
    __syncthreads();
    mx = red[0];
    const float sc = (mx > 0.f) ? 32512.f / mx : 0.f;
    if (tid == 0) s[r] = (mx > 0.f) ? mx / 32512.f : 0.f;
    int8_t* hr = hi + (size_t)r * K;
    int8_t* lr = lo + (size_t)r * K;
    for (int i = tid; i < K; i += 256) {
        const int a = __float2int_rn(x[i] * sc);
        const int h = (a + 128) >> 8;
        hr[i] = (int8_t)h;
        lr[i] = (int8_t)(a - (h << 8));
    }
}

__global__ void colmax_k(const float* __restrict__ W, float* __restrict__ cmax,
                         int K, int N)
{
    const int n = blockIdx.x * blockDim.x + threadIdx.x;
    if (n >= N) return;
    float m = 0.f;
    for (int k = 0; k < K; k++) m = fmaxf(m, fabsf(W[(size_t)k * N + n]));
    cmax[n] = m;
}

// W[K,N] -> transposed int8 limbs [N,K] with per-column(n) scale.
__global__ void quantWT(const float* __restrict__ W, const float* __restrict__ cmax,
                        int8_t* __restrict__ Thi, int8_t* __restrict__ Tlo,
                        float* __restrict__ sb, int Kd, int Nd)
{
    __shared__ float t[32][33];
    const int nb = blockIdx.x * 32, kb = blockIdx.y * 32;
    const int tx = threadIdx.x, ty = threadIdx.y;  // 32 x 8
#pragma unroll
    for (int i = 0; i < 4; i++)
        t[ty + i * 8][tx] = W[(size_t)(kb + ty + i * 8) * Nd + nb + tx];
    __syncthreads();
#pragma unroll
    for (int i = 0; i < 4; i++) {
        const int n = nb + ty + i * 8, k = kb + tx;
        const float cm = cmax[n];
        const float sc = (cm > 0.f) ? 32512.f / cm : 0.f;
        if (kb == 0 && tx == 0) sb[n] = (cm > 0.f) ? cm / 32512.f : 0.f;
        const int a = __float2int_rn(t[tx][ty + i * 8] * sc);
        const int h = (a + 128) >> 8;
        Thi[(size_t)n * Kd + k] = (int8_t)h;
        Tlo[(size_t)n * Kd + k] = (int8_t)(a - (h << 8));
    }
}

// ---------------------------------------------------------------------------
// int8 2-limb GEMM: C = dequant( 65536*hi.hi + 256*(hi.lo + lo.hi) ).
// Tile 128x128, k-block 64 int8 (2 MMA k-steps), 8 warps, warp 32x64.
// 3 IMMA per k32 vs 6 HMMA for bf16x3 -> 2x fewer MMA instructions.
// mode 0: fp32 C. mode 1: fp16 hi/lo (Ch, Cl).
// ---------------------------------------------------------------------------
#define GPADB 80                        // padded row bytes (64 data + 16 pad)
#define TILE_B (128 * GPADB)            // 10240 B per tensor tile
#define STAGE_B (4 * TILE_B)            // 40960
#define GSMEM_BYTES (2 * STAGE_B)       // 81920

__global__ __launch_bounds__(256, 1) void gemm_s8(
    const int8_t* __restrict__ Ahi, const int8_t* __restrict__ Alo,
    const int8_t* __restrict__ Bhi, const int8_t* __restrict__ Blo,
    const float* __restrict__ sa, const float* __restrict__ sbv,
    float* __restrict__ C, __half* __restrict__ Ch, __half* __restrict__ Cl,
    int mode, int M, int N, int K)
{
    extern __shared__ int8_t sm8[];
    const uint32_t sb_ = smem_u32(sm8);
    const int tid = threadIdx.x, lane = tid & 31, wid = tid >> 5;
    const int wm = wid & 3, wn = wid >> 2;
    const int row0 = blockIdx.y * 128, col0 = blockIdx.x * 128;

    int hh[2][8][4], mid[2][8][4];
#pragma unroll
    for (int mi = 0; mi < 2; mi++)
#pragma unroll
        for (int nf = 0; nf < 8; nf++)
#pragma unroll
            for (int e = 0; e < 4; e++) { hh[mi][nf][e] = 0; mid[mi][nf][e] = 0; }

    auto load_stage = [&](int s, int k0) {
        const uint32_t soff = (uint32_t)(s * STAGE_B);
#pragma unroll
        for (int t = 0; t < 2; t++) {
            const int i = tid + t * 256;
            const int r = i >> 2, ch = (i & 3) * 16;
            const size_t ga = (size_t)(row0 + r) * K + k0 + ch;
            const size_t gb = (size_t)(col0 + r) * K + k0 + ch;
            const uint32_t so = soff + (uint32_t)(r * GPADB + ch);
            cp_async16(sb_ + so + 0 * TILE_B, Ahi + ga);
            cp_async16(sb_ + so + 1 * TILE_B, Alo + ga);
            cp_async16(sb_ + so + 2 * TILE_B, Bhi + gb);
            cp_async16(sb_ + so + 3 * TILE_B, Blo + gb);
        }
    };

    // ldmatrix lane addressing (byte units; identical pattern to f16 k16)
    const int a_r  = lane & 15, a_kB = (lane >> 4) * 16;
    const int b_r  = (lane & 7) | ((lane & 16) >> 1);
    const int b_kB = (lane & 8) ? 16 : 0;

    const int nk = K >> 6;   // k-blocks of 64 int8
    load_stage(0, 0);
    cp_commit();

    for (int ki = 0; ki < nk; ki++) {
        if (ki + 1 < nk) {
            load_stage((ki + 1) & 1, (ki + 1) * 64);
            cp_commit();
            cp_wait<1>();
        } else {
            cp_wait<0>();
        }
        __syncthreads();

        const uint32_t base = sb_ + (uint32_t)((ki & 1) * STAGE_B);
#pragma unroll
        for (int ks = 0; ks < 2; ks++) {
            const int koff = ks * 32;   // bytes
            uint32_t ahi[2][4], alo[2][4];
#pragma unroll
            for (int mi = 0; mi < 2; mi++) {
                const uint32_t off =
                    (uint32_t)((wm * 32 + mi * 16 + a_r) * GPADB + koff + a_kB);
                ldm_x4(ahi[mi], base + 0 * TILE_B + off);
                ldm_x4(alo[mi], base + 1 * TILE_B + off);
            }
#pragma unroll
            for (int g = 0; g < 4; g++) {
                const uint32_t boff =
                    (uint32_t)((wn * 64 + g * 16 + b_r) * GPADB + koff + b_kB);
                uint32_t bhi[4], blo[4];
                ldm_x4(bhi, base + 2 * TILE_B + boff);
                ldm_x4(blo, base + 3 * TILE_B + boff);
                const int n0 = g * 2, n1 = g * 2 + 1;
                // hi*hi (scale 65536)
                mma_s8(hh[0][n0], ahi[0], bhi);
                mma_s8(hh[1][n0], ahi[1], bhi);
                mma_s8(hh[0][n1], ahi[0], bhi + 2);
                mma_s8(hh[1][n1], ahi[1], bhi + 2);
                // hi*lo + lo*hi (shared scale 256 -> shared accumulator)
                mma_s8(mid[0][n0], ahi[0], blo);
                mma_s8(mid[1][n0], ahi[1], blo);
                mma_s8(mid[0][n1], ahi[0], blo + 2);
                mma_s8(mid[1][n1], ahi[1], blo + 2);
                mma_s8(mid[0][n0], alo[0], bhi);
                mma_s8(mid[1][n0], alo[1], bhi);
                mma_s8(mid[0][n1], alo[0], bhi + 2);
                mma_s8(mid[1][n1], alo[1], bhi + 2);
            }
        }
        __syncthreads();
    }

    const int cr = lane >> 2, cc = (lane & 3) * 2;
#pragma unroll
    for (int mi = 0; mi < 2; mi++) {
        const int r0 = row0 + wm * 32 + mi * 16 + cr;
        const float s0 = sa[r0], s1 = sa[r0 + 8];
#pragma unroll
        for (int nf = 0; nf < 8; nf++) {
            const int c = col0 + wn * 64 + nf * 8 + cc;
            const float t0 = sbv[c], t1 = sbv[c + 1];
            const float v0 = (65536.f * (float)hh[mi][nf][0] + 256.f * (float)mid[mi][nf][0]) * s0 * t0;
            const float v1 = (65536.f * (float)hh[mi][nf][1] + 256.f * (float)mid[mi][nf][1]) * s0 * t1;
            const float v2 = (65536.f * (float)hh[mi][nf][2] + 256.f * (float)mid[mi][nf][2]) * s1 * t0;
            const float v3 = (65536.f * (float)hh[mi][nf][3] + 256.f * (float)mid[mi][nf][3]) * s1 * t1;
            if (mode == 0) {
                *(float2*)(C + (size_t)r0 * N + c) = make_float2(v0, v1);
                *(float2*)(C + (size_t)(r0 + 8) * N + c) = make_float2(v2, v3);
            } else {
                const __half h0 = __float2half_rn(v0), h1 = __float2half_rn(v1);
                const __half h2 = __float2half_rn(v2), h3 = __float2half_rn(v3);
                const size_t i0 = (size_t)r0 * N + c, i1 = (size_t)(r0 + 8) * N + c;
                *(uint32_t*)(Ch + i0) = pack_h2(h0, h1);
                *(uint32_t*)(Ch + i1) = pack_h2(h2, h3);
                *(uint32_t*)(Cl + i0) =
                    pack_h2(__float2half_rn(v0 - __half2float(h0)),
                            __float2half_rn(v1 - __half2float(h1)));
                *(uint32_t*)(Cl + i1) =
                    pack_h2(__float2half_rn(v2 - __half2float(h2)),
                            __float2half_rn(v3 - __half2float(h3)));
            }
        }
    }
}

// ---------------------------------------------------------------------------
// Tensorized flash attention (R13, validated): S = fp16x3, PV = single Ph*Vh.
// Output now plain fp32 ctx (quantized afterwards by rowquant).
// ---------------------------------------------------------------------------
#define APAD 72
#define ATILE (64 * APAD)
#define ASMEM_BYTES (7 * ATILE * 2)       // 64512 B
#define SCALE_LOG2E 0.18033688011112042f

__global__ __launch_bounds__(128, 2) void attn_mma(
    const __half* __restrict__ qh, const __half* __restrict__ ql,
    float* __restrict__ ctx)
{
    extern __shared__ __half smh[];
    __half* Qh = smh;
    __half* Ql = smh + ATILE;
    const uint32_t sQh = smem_u32(Qh), sQl = smem_u32(Ql);
    const uint32_t sK0 = smem_u32(smh + 2 * ATILE);
    const uint32_t sV0 = smem_u32(smh + 6 * ATILE);

    const int tid = threadIdx.x, lane = tid & 31, wid = tid >> 5;
    const int qt = blockIdx.x, h = blockIdx.y, b = blockIdx.z;
    const int q0 = qt * 64, wq = wid * 16;
    const int rs = 3 * Dd;
    const int n = qt + 1;

    const __half* QgH = qh + (size_t)b * Tt * rs + h * DH;
    const __half* QgL = ql + (size_t)b * Tt * rs + h * DH;
    const __half* KgH = QgH + Dd;
    const __half* KgL = QgL + Dd;
    const __half* VgH = QgH + 2 * Dd;

    auto load_k = [&](int s, int kt_) {
        const int k0 = kt_ * 64;
        const uint32_t dst = sK0 + (uint32_t)(s * 2 * ATILE * 2);
#pragma unroll
        for (int t = 0; t < 2; t++) {
            const __half* src = t ? KgL : KgH;
#pragma unroll
            for (int u = 0; u < 4; u++) {
                const int i = tid + u * 128;
                const int r = i >> 3, ch = i & 7;
                cp_async16(dst + (uint32_t)((t * ATILE + r * APAD + ch * 8) * 2),
                           src + (size_t)(k0 + r) * rs + ch * 8);
            }
        }
    };
    auto load_v = [&](int kt_) {
        const int k0 = kt_ * 64;
#pragma unroll
        for (int u = 0; u < 4; u++) {
            const int i = tid + u * 128;
            const int r = i >> 3, ch = i & 7;
            cp_async16(sV0 + (uint32_t)((r * APAD + ch * 8) * 2),
                       VgH + (size_t)(k0 + r) * rs + ch * 8);
        }
    };

    load_k(0, 0);
    load_v(0);
    cp_commit();
    if (n > 1) load_k(1, 1);
    cp_commit();

#pragma unroll
    for (int u = 0; u < 4; u++) {
        const int i = tid + u * 128;
        const int r = i >> 3, ch = i & 7;
        *(uint4*)(Qh + r * APAD + ch * 8) =
            *(const uint4*)(QgH + (size_t)(q0 + r) * rs + ch * 8);
        *(uint4*)(Ql + r * APAD + ch * 8) =
            *(const uint4*)(QgL + (size_t)(q0 + r) * rs + ch * 8);
    }

    cp_wait<1>();
    __syncthreads();

    const int a_r = lane & 15, a_k = (lane >> 4) << 3;
    const int b_r = (lane & 7) | ((lane & 16) >> 1);
    const int b_k = (lane & 8) ? 8 : 0;
    const int v_r = lane & 15, v_n = (lane >> 4) << 3;

    uint32_t qfh[4][4], qfl[4][4];
#pragma unroll
    for (int j = 0; j < 4; j++) {
        const uint32_t off = (uint32_t)(((wq + a_r) * APAD + j * 16 + a_k) * 2);
        ldm_x4(qfh[j], sQh + off);
        ldm_x4(qfl[j], sQl + off);
    }

    float o[8][4];
#pragma unroll
    for (int nf = 0; nf < 8; nf++)
#pragma unroll
        for (int e = 0; e < 4; e++) o[nf][e] = 0.f;
    float m_i[2] = {-1e30f, -1e30f}, l_i[2] = {0.f, 0.f};

    const int cr = lane >> 2, cc = (lane & 3) * 2;

    for (int kt = 0; kt < n; kt++) {
        const int k0 = kt * 64;
        if (kt > 0) {
            cp_wait<2>();
            __syncthreads();
        }

        float s[8][4];
#pragma unroll
        for (int nf = 0; nf < 8; nf++)
#pragma unroll
            for (int e = 0; e < 4; e++) s[nf][e] = 0.f;
        {
            const uint32_t skh = sK0 + (uint32_t)((kt & 1) * 2 * ATILE * 2);
            const uint32_t skl = skh + ATILE * 2;
#pragma unroll
            for (int j = 0; j < 4; j++) {
                uint32_t kh[4][4], kl[4][4];
#pragma unroll
                for (int g = 0; g < 4; g++) {
                    const uint32_t boff =
                        (uint32_t)(((g * 16 + b_r) * APAD + j * 16 + b_k) * 2);
                    ldm_x4(kh[g], skh + boff);
                    ldm_x4(kl[g], skl + boff);
                }
#pragma unroll
                for (int g = 0; g < 4; g++) {
                    mma_f16(s[g * 2],     qfh[j], kh[g]);
                    mma_f16(s[g * 2 + 1], qfh[j], kh[g] + 2);
                }
#pragma unroll
                for (int g = 0; g < 4; g++) {
                    mma_f16(s[g * 2],     qfh[j], kl[g]);
                    mma_f16(s[g * 2 + 1], qfh[j], kl[g] + 2);
                }
#pragma unroll
                for (int g = 0; g < 4; g++) {
                    mma_f16(s[g * 2],     qfl[j], kh[g]);
                    mma_f16(s[g * 2 + 1], qfl[j], kh[g] + 2);
                }
            }
        }

        const bool diag = (kt == qt);
#pragma unroll
        for (int nf = 0; nf < 8; nf++) {
#pragma unroll
            for (int e = 0; e < 4; e++) {
                float v = s[nf][e] * SCALE_LOG2E;
                if (diag) {
                    const int r = q0 + wq + cr + (e >> 1) * 8;
                    const int c = k0 + nf * 8 + cc + (e & 1);
                    if (c > r) v = -1e30f;
                }
                s[nf][e] = v;
            }
        }

#pragma unroll
        for (int hh = 0; hh < 2; hh++) {
            float tm = -1e30f;
#pragma unroll
            for (int nf = 0; nf < 8; nf++)
                tm = fmaxf(tm, fmaxf(s[nf][hh * 2], s[nf][hh * 2 + 1]));
            tm = fmaxf(tm, __shfl_xor_sync(0xffffffffu, tm, 1, 32));
            tm = fmaxf(tm, __shfl_xor_sync(0xffffffffu, tm, 2, 32));
            const float mn = fmaxf(m_i[hh], tm);
            const float al = ex2f(m_i[hh] - mn);
            float rl = 0.f;
#pragma unroll
            for (int nf = 0; nf < 8; nf++) {
                const float p0 = ex2f(s[nf][hh * 2] - mn);
                const float p1 = ex2f(s[nf][hh * 2 + 1] - mn);
                s[nf][hh * 2] = p0;
                s[nf][hh * 2 + 1] = p1;
                rl += p0 + p1;
            }
            rl += __shfl_xor_sync(0xffffffffu, rl, 1, 32);
            rl += __shfl_xor_sync(0xffffffffu, rl, 2, 32);
            l_i[hh] = l_i[hh] * al + rl;
            m_i[hh] = mn;
#pragma unroll
            for (int nf = 0; nf < 8; nf++) {
                o[nf][hh * 2] *= al;
                o[nf][hh * 2 + 1] *= al;
            }
        }

        uint32_t ph[4][4];
#pragma unroll
        for (int j = 0; j < 4; j++) {
#pragma unroll
            for (int q = 0; q < 4; q++) {
                const int nf = 2 * j + (q >> 1);
                ph[j][q] = pack_h2(__float2half_rn(s[nf][(q & 1) * 2]),
                                   __float2half_rn(s[nf][(q & 1) * 2 + 1]));
            }
        }

        cp_wait<1>();
        __syncthreads();

#pragma unroll
        for (int j = 0; j < 4; j++) {
            uint32_t vh[4][4];
#pragma unroll
            for (int g = 0; g < 4; g++) {
                const uint32_t voff =
                    (uint32_t)(((j * 16 + v_r) * APAD + g * 16 + v_n) * 2);
                ldm_x4_t(vh[g], sV0 + voff);
            }
#pragma unroll
            for (int g = 0; g < 4; g++) {
                mma_f16(o[g * 2],     ph[j], vh[g]);
                mma_f16(o[g * 2 + 1], ph[j], vh[g] + 2);
            }
        }
        __syncthreads();

        if (kt + 1 < n) load_v(kt + 1);
        cp_commit();
        if (kt + 2 < n) load_k(kt & 1, kt + 2);
        cp_commit();
    }

    const float inv0 = 1.f / l_i[0], inv1 = 1.f / l_i[1];
    const int row = b * Tt + q0 + wq + cr;
#pragma unroll
    for (int nf = 0; nf < 8; nf++) {
        const int c = h * DH + nf * 8 + cc;
        *(float2*)(ctx + (size_t)row * Dd + c) =
            make_float2(o[nf][0] * inv0, o[nf][1] * inv0);
        *(float2*)(ctx + (size_t)(row + 8) * Dd + c) =
            make_float2(o[nf][2] * inv1, o[nf][3] * inv1);
    }
}

// ---------------------------------------------------------------------------
// Launch
// ---------------------------------------------------------------------------
extern "C" void kernel_launch(void* const* d_in, const int* in_sizes, int n_in,
                              void* d_out, int out_size)
{
    (void)in_sizes; (void)n_in; (void)out_size;
    const float* x    = (const float*)d_in[0];
    const float* Wqkv = (const float*)d_in[1];
    const float* Wout = (const float*)d_in[2];
    float* out = (float*)d_out;

    __half *qh, *ql;
    float *ctx, *sa, *sbq, *sbo, *cmax;
    int8_t *a8h, *a8l, *wqh8, *wql8, *woh8, *wol8;
    cudaGetSymbolAddress((void**)&qh, g_qh);
    cudaGetSymbolAddress((void**)&ql, g_ql);
    cudaGetSymbolAddress((void**)&ctx, g_ctx);
    cudaGetSymbolAddress((void**)&a8h, g_a8h);
    cudaGetSymbolAddress((void**)&a8l, g_a8l);
    cudaGetSymbolAddress((void**)&sa, g_sa);
    cudaGetSymbolAddress((void**)&wqh8, g_wqh8);
    cudaGetSymbolAddress((void**)&wql8, g_wql8);
    cudaGetSymbolAddress((void**)&sbq, g_sbq);
    cudaGetSymbolAddress((void**)&woh8, g_woh8);
    cudaGetSymbolAddress((void**)&wol8, g_wol8);
    cudaGetSymbolAddress((void**)&sbo, g_sbo);
    cudaGetSymbolAddress((void**)&cmax, g_cmax);

    cudaFuncSetAttribute(gemm_s8,
                         cudaFuncAttributeMaxDynamicSharedMemorySize, GSMEM_BYTES);
    cudaFuncSetAttribute(attn_mma,
                         cudaFuncAttributeMaxDynamicSharedMemorySize, ASMEM_BYTES);

    // 1) quantize x (per-row) and W_qkv^T (per-column)
    rowquant<<<MROWS, 256>>>(x, a8h, a8l, sa, Dd);
    colmax_k<<<(3 * Dd) / 256, 256>>>(Wqkv, cmax, Dd, 3 * Dd);
    {
        dim3 grid(3 * Dd / 32, Dd / 32);
        quantWT<<<grid, dim3(32, 8)>>>(Wqkv, cmax, wqh8, wql8, sbq, Dd, 3 * Dd);
    }
    // 2) QKV GEMM (int8 2-limb) -> fp16 hi/lo qkv
    {
        dim3 grid(3 * Dd / 128, MROWS / 128);
        gemm_s8<<<grid, 256, GSMEM_BYTES>>>(a8h, a8l, wqh8, wql8, sa, sbq,
                                            nullptr, qh, ql, 1,
                                            MROWS, 3 * Dd, Dd);
    }
    // 3) attention -> fp32 ctx
    {
        dim3 grid(Tt / 64, Hh, Bb);
        attn_mma<<<grid, 128, ASMEM_BYTES>>>(qh, ql, ctx);
    }
    // 4) quantize ctx and W_out^T
    rowquant<<<MROWS, 256>>>(ctx, a8h, a8l, sa, Dd);
    colmax_k<<<Dd / 256, 256>>>(Wout, cmax, Dd, Dd);
    {
        dim3 grid(Dd / 32, Dd / 32);
        quantWT<<<grid, dim3(32, 8)>>>(Wout, cmax, woh8, wol8, sbo, Dd, Dd);
    }
    // 5) output GEMM (int8 2-limb) -> fp32 out
    {
        dim3 grid(Dd / 128, MROWS / 128);
        gemm_s8<<<grid, 256, GSMEM_BYTES>>>(a8h, a8l, woh8, wol8, sa, sbo,
                                            out, nullptr, nullptr, 0,
                                            MROWS, Dd, Dd);
    }
}

// round 15
// speedup vs baseline: 2.0457x; 2.0457x over previous
#include <cuda_runtime.h>
#include <cuda_bf16.h>
#include <cuda_fp16.h>
#include <cstdint>

#define Bb 4
#define Tt 2048
#define Dd 1024
#define Hh 16
#define DH 64
#define MROWS (Bb * Tt)   // 8192

// ---------------------------------------------------------------------------
// Scratch (__device__ globals: allocation-free rule)
// ---------------------------------------------------------------------------
__device__ __half g_qh[(size_t)MROWS * 3 * Dd];       // qkv fp16 hi  [8192,3072]
__device__ __half g_ql[(size_t)MROWS * 3 * Dd];       // qkv fp16 lo
__device__ __nv_bfloat16 g_ahi[(size_t)MROWS * Dd];   // x split
__device__ __nv_bfloat16 g_alo[(size_t)MROWS * Dd];
__device__ __nv_bfloat16 g_chi[(size_t)MROWS * Dd];   // ctx split (written by attn)
__device__ __nv_bfloat16 g_clo[(size_t)MROWS * Dd];
__device__ __nv_bfloat16 g_wqhi[(size_t)3 * Dd * Dd]; // W_qkv^T split [3072,1024]
__device__ __nv_bfloat16 g_wqlo[(size_t)3 * Dd * Dd];
__device__ __nv_bfloat16 g_wohi[(size_t)Dd * Dd];     // W_out^T split [1024,1024]
__device__ __nv_bfloat16 g_wolo[(size_t)Dd * Dd];

// ---------------------------------------------------------------------------
// PTX helpers (plain compute_103-legal)
// ---------------------------------------------------------------------------
__device__ __forceinline__ uint32_t smem_u32(const void* p) {
    uint32_t a;
    asm("{ .reg .u64 t; cvta.to.shared.u64 t, %1; cvt.u32.u64 %0, t; }"
        : "=r"(a) : "l"(p));
    return a;
}
__device__ __forceinline__ void cp_async16(uint32_t saddr, const void* gaddr) {
    asm volatile("cp.async.cg.shared.global [%0], [%1], 16;"
                 :: "r"(saddr), "l"(gaddr));
}
__device__ __forceinline__ void cp_commit() {
    asm volatile("cp.async.commit_group;" ::: "memory");
}
template <int N>
__device__ __forceinline__ void cp_wait() {
    asm volatile("cp.async.wait_group %0;" :: "n"(N) : "memory");
}
__device__ __forceinline__ void ldm_x4(uint32_t* r, uint32_t addr) {
    asm volatile("ldmatrix.sync.aligned.m8n8.x4.shared.b16 {%0,%1,%2,%3}, [%4];"
                 : "=r"(r[0]), "=r"(r[1]), "=r"(r[2]), "=r"(r[3]) : "r"(addr));
}
__device__ __forceinline__ void ldm_x4_t(uint32_t* r, uint32_t addr) {
    asm volatile("ldmatrix.sync.aligned.m8n8.x4.trans.shared.b16 {%0,%1,%2,%3}, [%4];"
                 : "=r"(r[0]), "=r"(r[1]), "=r"(r[2]), "=r"(r[3]) : "r"(addr));
}
__device__ __forceinline__ void mma_bf16(float* c, const uint32_t* a, const uint32_t* b) {
    asm volatile("mma.sync.aligned.m16n8k16.row.col.f32.bf16.bf16.f32 "
                 "{%0,%1,%2,%3}, {%4,%5,%6,%7}, {%8,%9}, {%0,%1,%2,%3};"
                 : "+f"(c[0]), "+f"(c[1]), "+f"(c[2]), "+f"(c[3])
                 : "r"(a[0]), "r"(a[1]), "r"(a[2]), "r"(a[3]), "r"(b[0]), "r"(b[1]));
}
__device__ __forceinline__ void mma_f16(float* c, const uint32_t* a, const uint32_t* b) {
    asm volatile("mma.sync.aligned.m16n8k16.row.col.f32.f16.f16.f32 "
                 "{%0,%1,%2,%3}, {%4,%5,%6,%7}, {%8,%9}, {%0,%1,%2,%3};"
                 : "+f"(c[0]), "+f"(c[1]), "+f"(c[2]), "+f"(c[3])
                 : "r"(a[0]), "r"(a[1]), "r"(a[2]), "r"(a[3]), "r"(b[0]), "r"(b[1]));
}
__device__ __forceinline__ uint32_t pack_h2(__half a, __half b) {
    __half2 h = __halves2half2(a, b);
    return *(uint32_t*)&h;
}
__device__ __forceinline__ uint32_t pack_bf2(__nv_bfloat16 a, __nv_bfloat16 b) {
    __nv_bfloat162 t = __halves2bfloat162(a, b);
    return *(uint32_t*)&t;
}
__device__ __forceinline__ float ex2f(float x) {
    float y;
    asm("ex2.approx.ftz.f32 %0, %1;" : "=f"(y) : "f"(x));
    return y;
}

// ---------------------------------------------------------------------------
// Split kernels (GEMM inputs): fp32 -> bf16 hi/lo
// ---------------------------------------------------------------------------
__global__ void split_kernel(const float* __restrict__ X,
                             __nv_bfloat16* __restrict__ hi,
                             __nv_bfloat16* __restrict__ lo, int n)
{
    int i = blockIdx.x * blockDim.x + threadIdx.x;
    if (i < n) {
        float v = X[i];
        __nv_bfloat16 h = __float2bfloat16(v);
        hi[i] = h;
        lo[i] = __float2bfloat16(v - __bfloat162float(h));
    }
}

__global__ void splitT_kernel(const float* __restrict__ W,
                              __nv_bfloat16* __restrict__ Thi,
                              __nv_bfloat16* __restrict__ Tlo, int Kd, int Nd)
{
    __shared__ float t[32][33];
    const int nb = blockIdx.x * 32, kb = blockIdx.y * 32;
    const int tx = threadIdx.x, ty = threadIdx.y;  // 32 x 8
#pragma unroll
    for (int i = 0; i < 4; i++)
        t[ty + i * 8][tx] = W[(size_t)(kb + ty + i * 8) * Nd + nb + tx];
    __syncthreads();
#pragma unroll
    for (int i = 0; i < 4; i++) {
        const int n = nb + ty + i * 8, k = kb + tx;
        const float v = t[tx][ty + i * 8];
        __nv_bfloat16 h = __float2bfloat16(v);
        Thi[(size_t)n * Kd + k] = h;
        Tlo[(size_t)n * Kd + k] = __float2bfloat16(v - __bfloat162float(h));
    }
}

// ---------------------------------------------------------------------------
// HMMA GEMM, bf16x3. mode 0: fp32 C.  mode 1: fp16 hi/lo (Ch, Cl).
// R15: __launch_bounds__(256, 1) — reg budget 128 -> 255. R11 proved extra
// CTAs/SM buy nothing for MMA-bound kernels; the 128-reg cap likely spilled
// (64 accum floats + fragments + addressing > 128). The R14 s8 run proved a
// 1-CTA/SM 256-thread GEMM CTA can keep the tensor pipe 82% busy.
// ---------------------------------------------------------------------------
#define GPAD 40
#define TILE_E (128 * GPAD)
#define STAGE_E (4 * TILE_E)
#define GSMEM_BYTES (2 * STAGE_E * 2)   // 81920

__global__ __launch_bounds__(256, 1) void gemm_mma3(
    const __nv_bfloat16* __restrict__ Ahi, const __nv_bfloat16* __restrict__ Alo,
    const __nv_bfloat16* __restrict__ Bhi, const __nv_bfloat16* __restrict__ Blo,
    float* __restrict__ C, __half* __restrict__ Ch, __half* __restrict__ Cl,
    int mode, int M, int N, int K)
{
    extern __shared__ __nv_bfloat16 sm[];
    const uint32_t sb = smem_u32(sm);
    const int tid = threadIdx.x, lane = tid & 31, wid = tid >> 5;
    const int wm = wid & 3, wn = wid >> 2;
    const int row0 = blockIdx.y * 128, col0 = blockIdx.x * 128;

    float acc[2][8][4];
#pragma unroll
    for (int mi = 0; mi < 2; mi++)
#pragma unroll
        for (int nf = 0; nf < 8; nf++)
#pragma unroll
            for (int e = 0; e < 4; e++) acc[mi][nf][e] = 0.f;

    auto load_stage = [&](int s, int k0) {
        const int soff = s * STAGE_E;
#pragma unroll
        for (int t = 0; t < 2; t++) {
            const int i = tid + t * 256;
            const int r = i >> 2, ch = i & 3;
            const int se = r * GPAD + ch * 8;
            const size_t ga = (size_t)(row0 + r) * K + k0 + ch * 8;
            const size_t gb = (size_t)(col0 + r) * K + k0 + ch * 8;
            cp_async16(sb + (uint32_t)((soff + 0 * TILE_E + se) * 2), Ahi + ga);
            cp_async16(sb + (uint32_t)((soff + 1 * TILE_E + se) * 2), Alo + ga);
            cp_async16(sb + (uint32_t)((soff + 2 * TILE_E + se) * 2), Bhi + gb);
            cp_async16(sb + (uint32_t)((soff + 3 * TILE_E + se) * 2), Blo + gb);
        }
    };

    const int a_r  = lane & 15, a_k = (lane >> 4) << 3;
    const int b_r  = (lane & 7) | ((lane & 16) >> 1);
    const int b_k  = (lane & 8) ? 8 : 0;

    const int nk = K >> 5;
    load_stage(0, 0);
    cp_commit();

    for (int ki = 0; ki < nk; ki++) {
        if (ki + 1 < nk) {
            load_stage((ki + 1) & 1, (ki + 1) * 32);
            cp_commit();
            cp_wait<1>();
        } else {
            cp_wait<0>();
        }
        __syncthreads();

        const uint32_t base = sb + (uint32_t)((ki & 1) * STAGE_E * 2);
#pragma unroll
        for (int ks = 0; ks < 2; ks++) {
            const int koff = ks * 16;
            uint32_t ahi[2][4], alo[2][4];
#pragma unroll
            for (int mi = 0; mi < 2; mi++) {
                const uint32_t off =
                    (uint32_t)(((wm * 32 + mi * 16 + a_r) * GPAD + koff + a_k) * 2);
                ldm_x4(ahi[mi], base + 0 * TILE_E * 2 + off);
                ldm_x4(alo[mi], base + 1 * TILE_E * 2 + off);
            }
#pragma unroll
            for (int g = 0; g < 4; g++) {
                const uint32_t boff =
                    (uint32_t)(((wn * 64 + g * 16 + b_r) * GPAD + koff + b_k) * 2);
                uint32_t bhi[4], blo[4];
                ldm_x4(bhi, base + 2 * TILE_E * 2 + boff);
                ldm_x4(blo, base + 3 * TILE_E * 2 + boff);
                const int n0 = g * 2, n1 = g * 2 + 1;
                mma_bf16(acc[0][n0], ahi[0], bhi);
                mma_bf16(acc[1][n0], ahi[1], bhi);
                mma_bf16(acc[0][n1], ahi[0], bhi + 2);
                mma_bf16(acc[1][n1], ahi[1], bhi + 2);
                mma_bf16(acc[0][n0], ahi[0], blo);
                mma_bf16(acc[1][n0], ahi[1], blo);
                mma_bf16(acc[0][n1], ahi[0], blo + 2);
                mma_bf16(acc[1][n1], ahi[1], blo + 2);
                mma_bf16(acc[0][n0], alo[0], bhi);
                mma_bf16(acc[1][n0], alo[1], bhi);
                mma_bf16(acc[0][n1], alo[0], bhi + 2);
                mma_bf16(acc[1][n1], alo[1], bhi + 2);
            }
        }
        __syncthreads();
    }

    const int cr = lane >> 2, cc = (lane & 3) * 2;
    if (mode == 0) {
#pragma unroll
        for (int mi = 0; mi < 2; mi++) {
            const int r0 = row0 + wm * 32 + mi * 16 + cr;
#pragma unroll
            for (int nf = 0; nf < 8; nf++) {
                const int c = col0 + wn * 64 + nf * 8 + cc;
                *(float2*)(C + (size_t)r0 * N + c) =
                    make_float2(acc[mi][nf][0], acc[mi][nf][1]);
                *(float2*)(C + (size_t)(r0 + 8) * N + c) =
                    make_float2(acc[mi][nf][2], acc[mi][nf][3]);
            }
        }
    } else {
#pragma unroll
        for (int mi = 0; mi < 2; mi++) {
            const int r0 = row0 + wm * 32 + mi * 16 + cr;
#pragma unroll
            for (int nf = 0; nf < 8; nf++) {
                const int c = col0 + wn * 64 + nf * 8 + cc;
#pragma unroll
                for (int hh = 0; hh < 2; hh++) {
                    const float x0 = acc[mi][nf][hh * 2];
                    const float x1 = acc[mi][nf][hh * 2 + 1];
                    const __half h0 = __float2half_rn(x0);
                    const __half h1 = __float2half_rn(x1);
                    const size_t idx = (size_t)(r0 + hh * 8) * N + c;
                    *(uint32_t*)(Ch + idx) = pack_h2(h0, h1);
                    *(uint32_t*)(Cl + idx) =
                        pack_h2(__float2half_rn(x0 - __half2float(h0)),
                                __float2half_rn(x1 - __half2float(h1)));
                }
            }
        }
    }
}

// ---------------------------------------------------------------------------
// Tensorized flash attention, causal (R13, validated at 222 us).
// S = fp16x3; PV = single Ph*Vh (softmax-diluted error).
// ---------------------------------------------------------------------------
#define APAD 72
#define ATILE (64 * APAD)                 // 4608 halves per tile
#define ASMEM_BYTES (7 * ATILE * 2)       // 64512 B
#define SCALE_LOG2E 0.18033688011112042f

__global__ __launch_bounds__(128, 2) void attn_mma(
    const __half* __restrict__ qh, const __half* __restrict__ ql,
    __nv_bfloat16* __restrict__ chi, __nv_bfloat16* __restrict__ clo)
{
    extern __shared__ __half smh[];
    __half* Qh = smh;
    __half* Ql = smh + ATILE;
    const uint32_t sQh = smem_u32(Qh), sQl = smem_u32(Ql);
    const uint32_t sK0 = smem_u32(smh + 2 * ATILE);   // K stages: s*(2*ATILE)
    const uint32_t sV0 = smem_u32(smh + 6 * ATILE);   // Vh only, single buffer

    const int tid = threadIdx.x, lane = tid & 31, wid = tid >> 5;
    const int qt = blockIdx.x, h = blockIdx.y, b = blockIdx.z;
    const int q0 = qt * 64, wq = wid * 16;
    const int rs = 3 * Dd;
    const int n = qt + 1;   // causal kv-tile count

    const __half* QgH = qh + (size_t)b * Tt * rs + h * DH;
    const __half* QgL = ql + (size_t)b * Tt * rs + h * DH;
    const __half* KgH = QgH + Dd;
    const __half* KgL = QgL + Dd;
    const __half* VgH = QgH + 2 * Dd;

    auto load_k = [&](int s, int kt_) {
        const int k0 = kt_ * 64;
        const uint32_t dst = sK0 + (uint32_t)(s * 2 * ATILE * 2);
#pragma unroll
        for (int t = 0; t < 2; t++) {
            const __half* src = t ? KgL : KgH;
#pragma unroll
            for (int u = 0; u < 4; u++) {
                const int i = tid + u * 128;
                const int r = i >> 3, ch = i & 7;
                cp_async16(dst + (uint32_t)((t * ATILE + r * APAD + ch * 8) * 2),
                           src + (size_t)(k0 + r) * rs + ch * 8);
            }
        }
    };
    auto load_v = [&](int kt_) {
        const int k0 = kt_ * 64;
#pragma unroll
        for (int u = 0; u < 4; u++) {
            const int i = tid + u * 128;
            const int r = i >> 3, ch = i & 7;
            cp_async16(sV0 + (uint32_t)((r * APAD + ch * 8) * 2),
                       VgH + (size_t)(k0 + r) * rs + ch * 8);
        }
    };

    // Prologue: C1={K0,V0}; C2={K1 or empty}
    load_k(0, 0);
    load_v(0);
    cp_commit();
    if (n > 1) load_k(1, 1);
    cp_commit();

    // Q tile: plain 16B copies of pre-split fp16
#pragma unroll
    for (int u = 0; u < 4; u++) {
        const int i = tid + u * 128;
        const int r = i >> 3, ch = i & 7;
        *(uint4*)(Qh + r * APAD + ch * 8) =
            *(const uint4*)(QgH + (size_t)(q0 + r) * rs + ch * 8);
        *(uint4*)(Ql + r * APAD + ch * 8) =
            *(const uint4*)(QgL + (size_t)(q0 + r) * rs + ch * 8);
    }

    cp_wait<1>();      // C1 done: K0 + V0 resident
    __syncthreads();

    // Preload Q A-fragments
    const int a_r = lane & 15, a_k = (lane >> 4) << 3;
    const int b_r = (lane & 7) | ((lane & 16) >> 1);
    const int b_k = (lane & 8) ? 8 : 0;
    const int v_r = lane & 15, v_n = (lane >> 4) << 3;

    uint32_t qfh[4][4], qfl[4][4];
#pragma unroll
    for (int j = 0; j < 4; j++) {
        const uint32_t off = (uint32_t)(((wq + a_r) * APAD + j * 16 + a_k) * 2);
        ldm_x4(qfh[j], sQh + off);
        ldm_x4(qfl[j], sQl + off);
    }

    float o[8][4];
#pragma unroll
    for (int nf = 0; nf < 8; nf++)
#pragma unroll
        for (int e = 0; e < 4; e++) o[nf][e] = 0.f;
    float m_i[2] = {-1e30f, -1e30f}, l_i[2] = {0.f, 0.f};

    const int cr = lane >> 2, cc = (lane & 3) * 2;

    for (int kt = 0; kt < n; kt++) {
        const int k0 = kt * 64;
        if (kt > 0) {
            cp_wait<2>();        // releases the K(kt) group
            __syncthreads();
        }

        // ---- S = Q K^T (fp16x3), term-sweep schedule ----
        float s[8][4];
#pragma unroll
        for (int nf = 0; nf < 8; nf++)
#pragma unroll
            for (int e = 0; e < 4; e++) s[nf][e] = 0.f;
        {
            const uint32_t skh = sK0 + (uint32_t)((kt & 1) * 2 * ATILE * 2);
            const uint32_t skl = skh + ATILE * 2;
#pragma unroll
            for (int j = 0; j < 4; j++) {
                uint32_t kh[4][4], kl[4][4];
#pragma unroll
                for (int g = 0; g < 4; g++) {
                    const uint32_t boff =
                        (uint32_t)(((g * 16 + b_r) * APAD + j * 16 + b_k) * 2);
                    ldm_x4(kh[g], skh + boff);
                    ldm_x4(kl[g], skl + boff);
                }
#pragma unroll
                for (int g = 0; g < 4; g++) {
                    mma_f16(s[g * 2],     qfh[j], kh[g]);
                    mma_f16(s[g * 2 + 1], qfh[j], kh[g] + 2);
                }
#pragma unroll
                for (int g = 0; g < 4; g++) {
                    mma_f16(s[g * 2],     qfh[j], kl[g]);
                    mma_f16(s[g * 2 + 1], qfh[j], kl[g] + 2);
                }
#pragma unroll
                for (int g = 0; g < 4; g++) {
                    mma_f16(s[g * 2],     qfl[j], kh[g]);
                    mma_f16(s[g * 2 + 1], qfl[j], kh[g] + 2);
                }
            }
        }

        // ---- scale + causal mask (base-2 domain) ----
        const bool diag = (kt == qt);
#pragma unroll
        for (int nf = 0; nf < 8; nf++) {
#pragma unroll
            for (int e = 0; e < 4; e++) {
                float v = s[nf][e] * SCALE_LOG2E;
                if (diag) {
                    const int r = q0 + wq + cr + (e >> 1) * 8;
                    const int c = k0 + nf * 8 + cc + (e & 1);
                    if (c > r) v = -1e30f;
                }
                s[nf][e] = v;
            }
        }

        // ---- online softmax ----
#pragma unroll
        for (int hh = 0; hh < 2; hh++) {
            float tm = -1e30f;
#pragma unroll
            for (int nf = 0; nf < 8; nf++)
                tm = fmaxf(tm, fmaxf(s[nf][hh * 2], s[nf][hh * 2 + 1]));
            tm = fmaxf(tm, __shfl_xor_sync(0xffffffffu, tm, 1, 32));
            tm = fmaxf(tm, __shfl_xor_sync(0xffffffffu, tm, 2, 32));
            const float mn = fmaxf(m_i[hh], tm);
            const float al = ex2f(m_i[hh] - mn);
            float rl = 0.f;
#pragma unroll
            for (int nf = 0; nf < 8; nf++) {
                const float p0 = ex2f(s[nf][hh * 2] - mn);
                const float p1 = ex2f(s[nf][hh * 2 + 1] - mn);
                s[nf][hh * 2] = p0;
                s[nf][hh * 2 + 1] = p1;
                rl += p0 + p1;
            }
            rl += __shfl_xor_sync(0xffffffffu, rl, 1, 32);
            rl += __shfl_xor_sync(0xffffffffu, rl, 2, 32);
            l_i[hh] = l_i[hh] * al + rl;
            m_i[hh] = mn;
#pragma unroll
            for (int nf = 0; nf < 8; nf++) {
                o[nf][hh * 2] *= al;
                o[nf][hh * 2 + 1] *= al;
            }
        }

        // ---- P -> fp16 A-fragments (hi only; overlaps the V wait) ----
        uint32_t ph[4][4];
#pragma unroll
        for (int j = 0; j < 4; j++) {
#pragma unroll
            for (int q = 0; q < 4; q++) {
                const int nf = 2 * j + (q >> 1);
                ph[j][q] = pack_h2(__float2half_rn(s[nf][(q & 1) * 2]),
                                   __float2half_rn(s[nf][(q & 1) * 2 + 1]));
            }
        }

        cp_wait<1>();            // releases the V(kt) group
        __syncthreads();

        // ---- O += Ph Vh (single product; softmax-diluted error) ----
#pragma unroll
        for (int j = 0; j < 4; j++) {
            uint32_t vh[4][4];
#pragma unroll
            for (int g = 0; g < 4; g++) {
                const uint32_t voff =
                    (uint32_t)(((j * 16 + v_r) * APAD + g * 16 + v_n) * 2);
                ldm_x4_t(vh[g], sV0 + voff);
            }
#pragma unroll
            for (int g = 0; g < 4; g++) {
                mma_f16(o[g * 2],     ph[j], vh[g]);
                mma_f16(o[g * 2 + 1], ph[j], vh[g] + 2);
            }
        }
        __syncthreads();         // all reads of V(kt) and K(kt) complete

        // ---- issue next loads (always 2 commits; empty groups legal) ----
        if (kt + 1 < n) load_v(kt + 1);
        cp_commit();
        if (kt + 2 < n) load_k(kt & 1, kt + 2);
        cp_commit();
    }

    // finalize: O /= l, write bf16 hi/lo ctx
    const float inv0 = 1.f / l_i[0], inv1 = 1.f / l_i[1];
    const int row = b * Tt + q0 + wq + cr;
#pragma unroll
    for (int nf = 0; nf < 8; nf++) {
        const int c = h * DH + nf * 8 + cc;
#pragma unroll
        for (int hh = 0; hh < 2; hh++) {
            const float inv = hh ? inv1 : inv0;
            const float v0 = o[nf][hh * 2] * inv;
            const float v1 = o[nf][hh * 2 + 1] * inv;
            const __nv_bfloat16 b0 = __float2bfloat16(v0);
            const __nv_bfloat16 b1 = __float2bfloat16(v1);
            const size_t idx = (size_t)(row + hh * 8) * Dd + c;
            *(uint32_t*)(chi + idx) = pack_bf2(b0, b1);
            *(uint32_t*)(clo + idx) =
                pack_bf2(__float2bfloat16(v0 - __bfloat162float(b0)),
                         __float2bfloat16(v1 - __bfloat162float(b1)));
        }
    }
}

// ---------------------------------------------------------------------------
// Launch
// ---------------------------------------------------------------------------
extern "C" void kernel_launch(void* const* d_in, const int* in_sizes, int n_in,
                              void* d_out, int out_size)
{
    (void)in_sizes; (void)n_in; (void)out_size;
    const float* x    = (const float*)d_in[0];
    const float* Wqkv = (const float*)d_in[1];
    const float* Wout = (const float*)d_in[2];
    float* out = (float*)d_out;

    __half *qh, *ql;
    __nv_bfloat16 *ahi, *alo, *chi, *clo, *wqhi, *wqlo, *wohi, *wolo;
    cudaGetSymbolAddress((void**)&qh, g_qh);
    cudaGetSymbolAddress((void**)&ql, g_ql);
    cudaGetSymbolAddress((void**)&ahi, g_ahi);
    cudaGetSymbolAddress((void**)&alo, g_alo);
    cudaGetSymbolAddress((void**)&chi, g_chi);
    cudaGetSymbolAddress((void**)&clo, g_clo);
    cudaGetSymbolAddress((void**)&wqhi, g_wqhi);
    cudaGetSymbolAddress((void**)&wqlo, g_wqlo);
    cudaGetSymbolAddress((void**)&wohi, g_wohi);
    cudaGetSymbolAddress((void**)&wolo, g_wolo);

    cudaFuncSetAttribute(gemm_mma3,
                         cudaFuncAttributeMaxDynamicSharedMemorySize, GSMEM_BYTES);
    cudaFuncSetAttribute(attn_mma,
                         cudaFuncAttributeMaxDynamicSharedMemorySize, ASMEM_BYTES);

    const int nA = MROWS * Dd;

    split_kernel<<<(nA + 255) / 256, 256>>>(x, ahi, alo, nA);
    {
        dim3 grid(3 * Dd / 32, Dd / 32);
        splitT_kernel<<<grid, dim3(32, 8)>>>(Wqkv, wqhi, wqlo, Dd, 3 * Dd);
    }
    {
        dim3 grid(3 * Dd / 128, MROWS / 128);
        gemm_mma3<<<grid, 256, GSMEM_BYTES>>>(ahi, alo, wqhi, wqlo,
                                              nullptr, qh, ql, 1,
                                              MROWS, 3 * Dd, Dd);
    }
    {
        dim3 grid(Tt / 64, Hh, Bb);
        attn_mma<<<grid, 128, ASMEM_BYTES>>>(qh, ql, chi, clo);
    }
    {
        dim3 grid(Dd / 32, Dd / 32);
        splitT_kernel<<<grid, dim3(32, 8)>>>(Wout, wohi, wolo, Dd, Dd);
    }
    {
        dim3 grid(Dd / 128, MROWS / 128);
        gemm_mma3<<<grid, 256, GSMEM_BYTES>>>(chi, clo, wohi, wolo,
                                              out, nullptr, nullptr, 0,
                                              MROWS, Dd, Dd);
    }
}

// round 17
// speedup vs baseline: 2.9226x; 1.4287x over previous
#include <cuda_runtime.h>
#include <cuda_fp16.h>
#include <cstdint>

#define Bb 4
#define Tt 2048
#define Dd 1024
#define Hh 16
#define DH 64
#define MROWS (Bb * Tt)   // 8192

// ---------------------------------------------------------------------------
// Scratch (__device__ globals: allocation-free rule)
// ---------------------------------------------------------------------------
__device__ __half g_qh[(size_t)MROWS * 3 * Dd];   // qkv fp16 hi
__device__ __half g_ql[(size_t)MROWS * 3 * Dd];   // qkv fp16 lo
__device__ __half g_xh[(size_t)MROWS * Dd];       // x as fp16 (hi only)
__device__ __half g_cf[(size_t)MROWS * Dd];       // ctx as fp16 (hi only)
__device__ __half g_wqh[(size_t)3 * Dd * Dd];     // W_qkv^T fp16 hi [3072,1024]
__device__ __half g_wql[(size_t)3 * Dd * Dd];     // W_qkv^T fp16 lo
__device__ __half g_woh[(size_t)Dd * Dd];         // W_out^T fp16 hi [1024,1024]
__device__ __half g_wol[(size_t)Dd * Dd];         // W_out^T fp16 lo

// ---------------------------------------------------------------------------
// PTX helpers (plain compute_103-legal)
// ---------------------------------------------------------------------------
__device__ __forceinline__ uint32_t smem_u32(const void* p) {
    uint32_t a;
    asm("{ .reg .u64 t; cvta.to.shared.u64 t, %1; cvt.u32.u64 %0, t; }"
        : "=r"(a) : "l"(p));
    return a;
}
__device__ __forceinline__ void cp_async16(uint32_t saddr, const void* gaddr) {
    asm volatile("cp.async.cg.shared.global [%0], [%1], 16;"
                 :: "r"(saddr), "l"(gaddr));
}
__device__ __forceinline__ void cp_commit() {
    asm volatile("cp.async.commit_group;" ::: "memory");
}
template <int N>
__device__ __forceinline__ void cp_wait() {
    asm volatile("cp.async.wait_group %0;" :: "n"(N) : "memory");
}
__device__ __forceinline__ void ldm_x4(uint32_t* r, uint32_t addr) {
    asm volatile("ldmatrix.sync.aligned.m8n8.x4.shared.b16 {%0,%1,%2,%3}, [%4];"
                 : "=r"(r[0]), "=r"(r[1]), "=r"(r[2]), "=r"(r[3]) : "r"(addr));
}
__device__ __forceinline__ void ldm_x4_t(uint32_t* r, uint32_t addr) {
    asm volatile("ldmatrix.sync.aligned.m8n8.x4.trans.shared.b16 {%0,%1,%2,%3}, [%4];"
                 : "=r"(r[0]), "=r"(r[1]), "=r"(r[2]), "=r"(r[3]) : "r"(addr));
}
__device__ __forceinline__ void mma_f16(float* c, const uint32_t* a, const uint32_t* b) {
    asm volatile("mma.sync.aligned.m16n8k16.row.col.f32.f16.f16.f32 "
                 "{%0,%1,%2,%3}, {%4,%5,%6,%7}, {%8,%9}, {%0,%1,%2,%3};"
                 : "+f"(c[0]), "+f"(c[1]), "+f"(c[2]), "+f"(c[3])
                 : "r"(a[0]), "r"(a[1]), "r"(a[2]), "r"(a[3]), "r"(b[0]), "r"(b[1]));
}
__device__ __forceinline__ uint32_t pack_h2(__half a, __half b) {
    __half2 h = __halves2half2(a, b);
    return *(uint32_t*)&h;
}
__device__ __forceinline__ float ex2f(float x) {
    float y;
    asm("ex2.approx.ftz.f32 %0, %1;" : "=f"(y) : "f"(x));
    return y;
}

// ---------------------------------------------------------------------------
// Conversion kernels
// ---------------------------------------------------------------------------
// fp32 -> fp16 (hi only; the dropped residual is the 1.5e-4 error term)
__global__ void half_kernel(const float* __restrict__ X,
                            __half* __restrict__ H, int n)
{
    int i = blockIdx.x * blockDim.x + threadIdx.x;
    if (i < n) H[i] = __float2half_rn(X[i]);
}

// W[K,N] row-major -> W^T fp16 hi/lo: [N,K] (K-major, MMA B operand)
__global__ void splitT_kernel(const float* __restrict__ W,
                              __half* __restrict__ Thi,
                              __half* __restrict__ Tlo, int Kd, int Nd)
{
    __shared__ float t[32][33];
    const int nb = blockIdx.x * 32, kb = blockIdx.y * 32;
    const int tx = threadIdx.x, ty = threadIdx.y;  // 32 x 8
#pragma unroll
    for (int i = 0; i < 4; i++)
        t[ty + i * 8][tx] = W[(size_t)(kb + ty + i * 8) * Nd + nb + tx];
    __syncthreads();
#pragma unroll
    for (int i = 0; i < 4; i++) {
        const int n = nb + ty + i * 8, k = kb + tx;
        const float v = t[tx][ty + i * 8];
        const __half h = __float2half_rn(v);
        Thi[(size_t)n * Kd + k] = h;
        Tlo[(size_t)n * Kd + k] = __float2half_rn(v - __half2float(h));
    }
}

// ---------------------------------------------------------------------------
// HMMA GEMM, fp16x2: C = Ah*Bh + Ah*Bl (Al dropped; incoherent 1.5e-4).
// Tile 128x128x32, 8 warps (4Mx2N), 2 CTAs/SM (R15 proved 1 CTA is worse).
// 8 MMAs per g vs 12 for bf16x3 -> MMA count x2/3; smem 3 tiles/stage.
// mode 0: fp32 C. mode 1: fp16 hi/lo (Ch, Cl) for the attention consumer.
// ---------------------------------------------------------------------------
#define GPAD 40
#define TILE_E (128 * GPAD)             // 5120 halves
#define STAGE_E (3 * TILE_E)            // A, Bh, Bl
#define GSMEM_BYTES (2 * STAGE_E * 2)   // 61440

__global__ __launch_bounds__(256, 2) void gemm_f16x2(
    const __half* __restrict__ A,
    const __half* __restrict__ Bhi, const __half* __restrict__ Blo,
    float* __restrict__ C, __half* __restrict__ Ch, __half* __restrict__ Cl,
    int mode, int M, int N, int K)
{
    extern __shared__ __half sm[];
    const uint32_t sb = smem_u32(sm);
    const int tid = threadIdx.x, lane = tid & 31, wid = tid >> 5;
    const int wm = wid & 3, wn = wid >> 2;
    const int row0 = blockIdx.y * 128, col0 = blockIdx.x * 128;

    float acc[2][8][4];
#pragma unroll
    for (int mi = 0; mi < 2; mi++)
#pragma unroll
        for (int nf = 0; nf < 8; nf++)
#pragma unroll
            for (int e = 0; e < 4; e++) acc[mi][nf][e] = 0.f;

    auto load_stage = [&](int s, int k0) {
        const int soff = s * STAGE_E;
#pragma unroll
        for (int t = 0; t < 2; t++) {
            const int i = tid + t * 256;
            const int r = i >> 2, ch = i & 3;
            const int se = r * GPAD + ch * 8;
            const size_t ga = (size_t)(row0 + r) * K + k0 + ch * 8;
            const size_t gb = (size_t)(col0 + r) * K + k0 + ch * 8;
            cp_async16(sb + (uint32_t)((soff + 0 * TILE_E + se) * 2), A + ga);
            cp_async16(sb + (uint32_t)((soff + 1 * TILE_E + se) * 2), Bhi + gb);
            cp_async16(sb + (uint32_t)((soff + 2 * TILE_E + se) * 2), Blo + gb);
        }
    };

    const int a_r  = lane & 15, a_k = (lane >> 4) << 3;
    const int b_r  = (lane & 7) | ((lane & 16) >> 1);
    const int b_k  = (lane & 8) ? 8 : 0;

    const int nk = K >> 5;
    load_stage(0, 0);
    cp_commit();

    for (int ki = 0; ki < nk; ki++) {
        if (ki + 1 < nk) {
            load_stage((ki + 1) & 1, (ki + 1) * 32);
            cp_commit();
            cp_wait<1>();
        } else {
            cp_wait<0>();
        }
        __syncthreads();

        const uint32_t base = sb + (uint32_t)((ki & 1) * STAGE_E * 2);
#pragma unroll
        for (int ks = 0; ks < 2; ks++) {
            const int koff = ks * 16;
            uint32_t ah[2][4];
#pragma unroll
            for (int mi = 0; mi < 2; mi++) {
                const uint32_t off =
                    (uint32_t)(((wm * 32 + mi * 16 + a_r) * GPAD + koff + a_k) * 2);
                ldm_x4(ah[mi], base + 0 * TILE_E * 2 + off);
            }
#pragma unroll
            for (int g = 0; g < 4; g++) {
                const uint32_t boff =
                    (uint32_t)(((wn * 64 + g * 16 + b_r) * GPAD + koff + b_k) * 2);
                uint32_t bhi[4], blo[4];
                ldm_x4(bhi, base + 1 * TILE_E * 2 + boff);
                ldm_x4(blo, base + 2 * TILE_E * 2 + boff);
                const int n0 = g * 2, n1 = g * 2 + 1;
                // term 1: Ah * Bh
                mma_f16(acc[0][n0], ah[0], bhi);
                mma_f16(acc[1][n0], ah[1], bhi);
                mma_f16(acc[0][n1], ah[0], bhi + 2);
                mma_f16(acc[1][n1], ah[1], bhi + 2);
                // term 2: Ah * Bl
                mma_f16(acc[0][n0], ah[0], blo);
                mma_f16(acc[1][n0], ah[1], blo);
                mma_f16(acc[0][n1], ah[0], blo + 2);
                mma_f16(acc[1][n1], ah[1], blo + 2);
            }
        }
        __syncthreads();
    }

    const int cr = lane >> 2, cc = (lane & 3) * 2;
    if (mode == 0) {
#pragma unroll
        for (int mi = 0; mi < 2; mi++) {
            const int r0 = row0 + wm * 32 + mi * 16 + cr;
#pragma unroll
            for (int nf = 0; nf < 8; nf++) {
                const int c = col0 + wn * 64 + nf * 8 + cc;
                *(float2*)(C + (size_t)r0 * N + c) =
                    make_float2(acc[mi][nf][0], acc[mi][nf][1]);
                *(float2*)(C + (size_t)(r0 + 8) * N + c) =
                    make_float2(acc[mi][nf][2], acc[mi][nf][3]);
            }
        }
    } else {
#pragma unroll
        for (int mi = 0; mi < 2; mi++) {
            const int r0 = row0 + wm * 32 + mi * 16 + cr;
#pragma unroll
            for (int nf = 0; nf < 8; nf++) {
                const int c = col0 + wn * 64 + nf * 8 + cc;
#pragma unroll
                for (int hh = 0; hh < 2; hh++) {
                    const float x0 = acc[mi][nf][hh * 2];
                    const float x1 = acc[mi][nf][hh * 2 + 1];
                    const __half h0 = __float2half_rn(x0);
                    const __half h1 = __float2half_rn(x1);
                    const size_t idx = (size_t)(r0 + hh * 8) * N + c;
                    *(uint32_t*)(Ch + idx) = pack_h2(h0, h1);
                    *(uint32_t*)(Cl + idx) =
                        pack_h2(__float2half_rn(x0 - __half2float(h0)),
                                __float2half_rn(x1 - __half2float(h1)));
                }
            }
        }
    }
}

// ---------------------------------------------------------------------------
// Tensorized flash attention, causal (R13 core, validated at 222 us).
// S = fp16x3; PV = single Ph*Vh. Output: single fp16 ctx tensor.
// ---------------------------------------------------------------------------
#define APAD 72
#define ATILE (64 * APAD)                 // 4608 halves per tile
#define ASMEM_BYTES (7 * ATILE * 2)       // 64512 B
#define SCALE_LOG2E 0.18033688011112042f

__global__ __launch_bounds__(128, 2) void attn_mma(
    const __half* __restrict__ qh, const __half* __restrict__ ql,
    __half* __restrict__ cf)
{
    extern __shared__ __half smh[];
    __half* Qh = smh;
    __half* Ql = smh + ATILE;
    const uint32_t sQh = smem_u32(Qh), sQl = smem_u32(Ql);
    const uint32_t sK0 = smem_u32(smh + 2 * ATILE);   // K stages: s*(2*ATILE)
    const uint32_t sV0 = smem_u32(smh + 6 * ATILE);   // Vh only, single buffer

    const int tid = threadIdx.x, lane = tid & 31, wid = tid >> 5;
    const int qt = blockIdx.x, h = blockIdx.y, b = blockIdx.z;
    const int q0 = qt * 64, wq = wid * 16;
    const int rs = 3 * Dd;
    const int n = qt + 1;   // causal kv-tile count

    const __half* QgH = qh + (size_t)b * Tt * rs + h * DH;
    const __half* QgL = ql + (size_t)b * Tt * rs + h * DH;
    const __half* KgH = QgH + Dd;
    const __half* KgL = QgL + Dd;
    const __half* VgH = QgH + 2 * Dd;

    auto load_k = [&](int s, int kt_) {
        const int k0 = kt_ * 64;
        const uint32_t dst = sK0 + (uint32_t)(s * 2 * ATILE * 2);
#pragma unroll
        for (int t = 0; t < 2; t++) {
            const __half* src = t ? KgL : KgH;
#pragma unroll
            for (int u = 0; u < 4; u++) {
                const int i = tid + u * 128;
                const int r = i >> 3, ch = i & 7;
                cp_async16(dst + (uint32_t)((t * ATILE + r * APAD + ch * 8) * 2),
                           src + (size_t)(k0 + r) * rs + ch * 8);
            }
        }
    };
    auto load_v = [&](int kt_) {
        const int k0 = kt_ * 64;
#pragma unroll
        for (int u = 0; u < 4; u++) {
            const int i = tid + u * 128;
            const int r = i >> 3, ch = i & 7;
            cp_async16(sV0 + (uint32_t)((r * APAD + ch * 8) * 2),
                       VgH + (size_t)(k0 + r) * rs + ch * 8);
        }
    };

    // Prologue: C1={K0,V0}; C2={K1 or empty}
    load_k(0, 0);
    load_v(0);
    cp_commit();
    if (n > 1) load_k(1, 1);
    cp_commit();

    // Q tile: plain 16B copies of pre-split fp16
#pragma unroll
    for (int u = 0; u < 4; u++) {
        const int i = tid + u * 128;
        const int r = i >> 3, ch = i & 7;
        *(uint4*)(Qh + r * APAD + ch * 8) =
            *(const uint4*)(QgH + (size_t)(q0 + r) * rs + ch * 8);
        *(uint4*)(Ql + r * APAD + ch * 8) =
            *(const uint4*)(QgL + (size_t)(q0 + r) * rs + ch * 8);
    }

    cp_wait<1>();      // C1 done: K0 + V0 resident
    __syncthreads();

    // Preload Q A-fragments
    const int a_r = lane & 15, a_k = (lane >> 4) << 3;
    const int b_r = (lane & 7) | ((lane & 16) >> 1);
    const int b_k = (lane & 8) ? 8 : 0;
    const int v_r = lane & 15, v_n = (lane >> 4) << 3;

    uint32_t qfh[4][4], qfl[4][4];
#pragma unroll
    for (int j = 0; j < 4; j++) {
        const uint32_t off = (uint32_t)(((wq + a_r) * APAD + j * 16 + a_k) * 2);
        ldm_x4(qfh[j], sQh + off);
        ldm_x4(qfl[j], sQl + off);
    }

    float o[8][4];
#pragma unroll
    for (int nf = 0; nf < 8; nf++)
#pragma unroll
        for (int e = 0; e < 4; e++) o[nf][e] = 0.f;
    float m_i[2] = {-1e30f, -1e30f}, l_i[2] = {0.f, 0.f};

    const int cr = lane >> 2, cc = (lane & 3) * 2;

    for (int kt = 0; kt < n; kt++) {
        const int k0 = kt * 64;
        if (kt > 0) {
            cp_wait<2>();        // releases the K(kt) group
            __syncthreads();
        }

        // ---- S = Q K^T (fp16x3), term-sweep schedule ----
        float s[8][4];
#pragma unroll
        for (int nf = 0; nf < 8; nf++)
#pragma unroll
            for (int e = 0; e < 4; e++) s[nf][e] = 0.f;
        {
            const uint32_t skh = sK0 + (uint32_t)((kt & 1) * 2 * ATILE * 2);
            const uint32_t skl = skh + ATILE * 2;
#pragma unroll
            for (int j = 0; j < 4; j++) {
                uint32_t kh[4][4], kl[4][4];
#pragma unroll
                for (int g = 0; g < 4; g++) {
                    const uint32_t boff =
                        (uint32_t)(((g * 16 + b_r) * APAD + j * 16 + b_k) * 2);
                    ldm_x4(kh[g], skh + boff);
                    ldm_x4(kl[g], skl + boff);
                }
#pragma unroll
                for (int g = 0; g < 4; g++) {
                    mma_f16(s[g * 2],     qfh[j], kh[g]);
                    mma_f16(s[g * 2 + 1], qfh[j], kh[g] + 2);
                }
#pragma unroll
                for (int g = 0; g < 4; g++) {
                    mma_f16(s[g * 2],     qfh[j], kl[g]);
                    mma_f16(s[g * 2 + 1], qfh[j], kl[g] + 2);
                }
#pragma unroll
                for (int g = 0; g < 4; g++) {
                    mma_f16(s[g * 2],     qfl[j], kh[g]);
                    mma_f16(s[g * 2 + 1], qfl[j], kh[g] + 2);
                }
            }
        }

        // ---- scale + causal mask (base-2 domain) ----
        const bool diag = (kt == qt);
#pragma unroll
        for (int nf = 0; nf < 8; nf++) {
#pragma unroll
            for (int e = 0; e < 4; e++) {
                float v = s[nf][e] * SCALE_LOG2E;
                if (diag) {
                    const int r = q0 + wq + cr + (e >> 1) * 8;
                    const int c = k0 + nf * 8 + cc + (e & 1);
                    if (c > r) v = -1e30f;
                }
                s[nf][e] = v;
            }
        }

        // ---- online softmax ----
#pragma unroll
        for (int hh = 0; hh < 2; hh++) {
            float tm = -1e30f;
#pragma unroll
            for (int nf = 0; nf < 8; nf++)
                tm = fmaxf(tm, fmaxf(s[nf][hh * 2], s[nf][hh * 2 + 1]));
            tm = fmaxf(tm, __shfl_xor_sync(0xffffffffu, tm, 1, 32));
            tm = fmaxf(tm, __shfl_xor_sync(0xffffffffu, tm, 2, 32));
            const float mn = fmaxf(m_i[hh], tm);
            const float al = ex2f(m_i[hh] - mn);
            float rl = 0.f;
#pragma unroll
            for (int nf = 0; nf < 8; nf++) {
                const float p0 = ex2f(s[nf][hh * 2] - mn);
                const float p1 = ex2f(s[nf][hh * 2 + 1] - mn);
                s[nf][hh * 2] = p0;
                s[nf][hh * 2 + 1] = p1;
                rl += p0 + p1;
            }
            rl += __shfl_xor_sync(0xffffffffu, rl, 1, 32);
            rl += __shfl_xor_sync(0xffffffffu, rl, 2, 32);
            l_i[hh] = l_i[hh] * al + rl;
            m_i[hh] = mn;
#pragma unroll
            for (int nf = 0; nf < 8; nf++) {
                o[nf][hh * 2] *= al;
                o[nf][hh * 2 + 1] *= al;
            }
        }

        // ---- P -> fp16 A-fragments (hi only; overlaps the V wait) ----
        uint32_t ph[4][4];
#pragma unroll
        for (int j = 0; j < 4; j++) {
#pragma unroll
            for (int q = 0; q < 4; q++) {
                const int nf = 2 * j + (q >> 1);
                ph[j][q] = pack_h2(__float2half_rn(s[nf][(q & 1) * 2]),
                                   __float2half_rn(s[nf][(q & 1) * 2 + 1]));
            }
        }

        cp_wait<1>();            // releases the V(kt) group
        __syncthreads();

        // ---- O += Ph Vh (single product; softmax-diluted error) ----
#pragma unroll
        for (int j = 0; j < 4; j++) {
            uint32_t vh[4][4];
#pragma unroll
            for (int g = 0; g < 4; g++) {
                const uint32_t voff =
                    (uint32_t)(((j * 16 + v_r) * APAD + g * 16 + v_n) * 2);
                ldm_x4_t(vh[g], sV0 + voff);
            }
#pragma unroll
            for (int g = 0; g < 4; g++) {
                mma_f16(o[g * 2],     ph[j], vh[g]);
                mma_f16(o[g * 2 + 1], ph[j], vh[g] + 2);
            }
        }
        __syncthreads();         // all reads of V(kt) and K(kt) complete

        // ---- issue next loads (always 2 commits; empty groups legal) ----
        if (kt + 1 < n) load_v(kt + 1);
        cp_commit();
        if (kt + 2 < n) load_k(kt & 1, kt + 2);
        cp_commit();
    }

    // finalize: O /= l, write fp16 ctx (single tensor)
    const float inv0 = 1.f / l_i[0], inv1 = 1.f / l_i[1];
    const int row = b * Tt + q0 + wq + cr;
#pragma unroll
    for (int nf = 0; nf < 8; nf++) {
        const int c = h * DH + nf * 8 + cc;
        *(uint32_t*)(cf + (size_t)row * Dd + c) =
            pack_h2(__float2half_rn(o[nf][0] * inv0),
                    __float2half_rn(o[nf][1] * inv0));
        *(uint32_t*)(cf + (size_t)(row + 8) * Dd + c) =
            pack_h2(__float2half_rn(o[nf][2] * inv1),
                    __float2half_rn(o[nf][3] * inv1));
    }
}

// ---------------------------------------------------------------------------
// Launch
// ---------------------------------------------------------------------------
extern "C" void kernel_launch(void* const* d_in, const int* in_sizes, int n_in,
                              void* d_out, int out_size)
{
    (void)in_sizes; (void)n_in; (void)out_size;
    const float* x    = (const float*)d_in[0];
    const float* Wqkv = (const float*)d_in[1];
    const float* Wout = (const float*)d_in[2];
    float* out = (float*)d_out;

    __half *qh, *ql, *xh, *cf, *wqh, *wql, *woh, *wol;
    cudaGetSymbolAddress((void**)&qh, g_qh);
    cudaGetSymbolAddress((void**)&ql, g_ql);
    cudaGetSymbolAddress((void**)&xh, g_xh);
    cudaGetSymbolAddress((void**)&cf, g_cf);
    cudaGetSymbolAddress((void**)&wqh, g_wqh);
    cudaGetSymbolAddress((void**)&wql, g_wql);
    cudaGetSymbolAddress((void**)&woh, g_woh);
    cudaGetSymbolAddress((void**)&wol, g_wol);

    cudaFuncSetAttribute(gemm_f16x2,
                         cudaFuncAttributeMaxDynamicSharedMemorySize, GSMEM_BYTES);
    cudaFuncSetAttribute(attn_mma,
                         cudaFuncAttributeMaxDynamicSharedMemorySize, ASMEM_BYTES);

    const int nA = MROWS * Dd;

    // 1) x -> fp16
    half_kernel<<<(nA + 255) / 256, 256>>>(x, xh, nA);
    // 2) W_qkv^T fp16 hi/lo
    {
        dim3 grid(3 * Dd / 32, Dd / 32);
        splitT_kernel<<<grid, dim3(32, 8)>>>(Wqkv, wqh, wql, Dd, 3 * Dd);
    }
    // 3) QKV GEMM (fp16x2) -> fp16 hi/lo qkv
    {
        dim3 grid(3 * Dd / 128, MROWS / 128);
        gemm_f16x2<<<grid, 256, GSMEM_BYTES>>>(xh, wqh, wql,
                                               nullptr, qh, ql, 1,
                                               MROWS, 3 * Dd, Dd);
    }
    // 4) attention -> fp16 ctx
    {
        dim3 grid(Tt / 64, Hh, Bb);
        attn_mma<<<grid, 128, ASMEM_BYTES>>>(qh, ql, cf);
    }
    // 5) W_out^T fp16 hi/lo
    {
        dim3 grid(Dd / 32, Dd / 32);
        splitT_kernel<<<grid, dim3(32, 8)>>>(Wout, woh, wol, Dd, Dd);
    }
    // 6) output GEMM (fp16x2) -> fp32 out
    {
        dim3 grid(Dd / 128, MROWS / 128);
        gemm_f16x2<<<grid, 256, GSMEM_BYTES>>>(cf, woh, wol,
                                               out, nullptr, nullptr, 0,
                                               MROWS, Dd, Dd);
    }
}